// round 1
// baseline (speedup 1.0000x reference)
#include <cuda_runtime.h>
#include <cstdint>

// Problem constants (fixed shapes per reference)
#define BATCH   8192
#define BOX     10
#define PAIR    90          // BOX*(BOX-1)
#define NUM_OT  151
#define NUM_QT  65
// out elements = 65*90*151*151 = 133,385,850

// ---------------------------------------------------------------------------
// Kernel 1: vectorized copy score_matrix -> out (the HBM-bound bulk).
// ---------------------------------------------------------------------------
__global__ void copy_f4_kernel(const float4* __restrict__ src,
                               float4* __restrict__ dst,
                               long long n4,
                               const float* __restrict__ src_tail,
                               float* __restrict__ dst_tail,
                               int n_tail)
{
    long long i = (long long)blockIdx.x * blockDim.x + threadIdx.x;
    long long stride = (long long)gridDim.x * blockDim.x;
    for (; i < n4; i += stride) {
        dst[i] = src[i];
    }
    // scalar tail (n_tail < 4), handled once by global thread 0
    if (blockIdx.x == 0 && threadIdx.x == 0) {
        for (int t = 0; t < n_tail; t++) dst_tail[t] = src_tail[t];
    }
}

// ---------------------------------------------------------------------------
// Kernel 2: scatter-add of attention pair-products.
// One thread per (batch, pair) element: 8192*90 = 737,280 threads.
// ---------------------------------------------------------------------------
__global__ void scatter_kernel(const int*   __restrict__ obj_label,  // [BATCH, BOX]
                               const int*   __restrict__ qus_type,   // [BATCH]
                               const float* __restrict__ attention,  // [BATCH, BOX]
                               float*       __restrict__ out)        // [NUM_QT, PAIR, NUM_OT, NUM_OT]
{
    int t = blockIdx.x * blockDim.x + threadIdx.x;
    if (t >= BATCH * PAIR) return;

    int b = t / PAIR;
    int p = t - b * PAIR;

    // pair p -> (i, j), row-major over off-diagonal mask:
    // i = p / (BOX-1); j enumerates all indices != i in increasing order.
    int i  = p / (BOX - 1);
    int jj = p - i * (BOX - 1);
    int j  = jj + (jj >= i ? 1 : 0);

    const int*   lab = obj_label + b * BOX;
    const float* att = attention + b * BOX;

    int   ol1 = lab[j];          // obj_label[b, j]
    int   ol2 = lab[i];          // obj_label[b, i]
    float val = att[j] * att[i]; // at1 * at2
    int   qt  = qus_type[b];

    size_t idx = (((size_t)qt * PAIR + p) * NUM_OT + (size_t)ol1) * NUM_OT + (size_t)ol2;
    atomicAdd(out + idx, val);
}

// ---------------------------------------------------------------------------
// Launch
// ---------------------------------------------------------------------------
extern "C" void kernel_launch(void* const* d_in, const int* in_sizes, int n_in,
                              void* d_out, int out_size)
{
    const int*   obj_label    = (const int*)  d_in[0]; // [8192,10] int32
    const int*   qus_type     = (const int*)  d_in[1]; // [8192]    int32
    const float* attention    = (const float*)d_in[2]; // [8192,10] float32
    const float* score_matrix = (const float*)d_in[3]; // [65,90,151,151] float32
    float*       out          = (float*)d_out;

    long long n  = (long long)out_size;          // 133,385,850
    long long n4 = n >> 2;                       // float4 count
    int n_tail   = (int)(n - (n4 << 2));         // 2

    // Copy: saturate HBM. ~4 waves of 256-thread blocks across 148 SMs.
    {
        int threads = 256;
        int blocks  = 148 * 16;                  // grid-stride covers the rest
        copy_f4_kernel<<<blocks, threads>>>(
            (const float4*)score_matrix, (float4*)out, n4,
            score_matrix + (n4 << 2), out + (n4 << 2), n_tail);
    }

    // Scatter-add (same stream -> ordered after the copy).
    {
        int total   = BATCH * PAIR;              // 737,280
        int threads = 256;
        int blocks  = (total + threads - 1) / threads;
        scatter_kernel<<<blocks, threads>>>(obj_label, qus_type, attention, out);
    }
}

// round 2
// speedup vs baseline: 1.0181x; 1.0181x over previous
#include <cuda_runtime.h>
#include <cstdint>

// Problem constants (fixed shapes per reference)
#define BATCH   8192
#define BOX     10
#define PAIR    90          // BOX*(BOX-1)
#define NUM_OT  151
#define NUM_QT  65
// out elements = 65*90*151*151 = 133,385,850

// ---------------------------------------------------------------------------
// Kernel 1: streaming copy score_matrix -> out.
// .cs (evict-first) hints on both load and store: both streams are 533MB,
// far larger than L2 (126MB); caching either is pure pollution, and
// streaming stores should avoid write-allocate reads of dst lines.
// 4x unrolled grid-stride for memory-level parallelism (front-batched LDGs).
// ---------------------------------------------------------------------------
__global__ void __launch_bounds__(512)
copy_stream_kernel(const float4* __restrict__ src,
                   float4* __restrict__ dst,
                   long long n4,
                   const float* __restrict__ src_tail,
                   float* __restrict__ dst_tail,
                   int n_tail)
{
    const long long stride = (long long)gridDim.x * blockDim.x;
    long long i = (long long)blockIdx.x * blockDim.x + threadIdx.x;

    // Main unrolled loop: 4 independent loads in flight, then 4 stores.
    for (; i + 3 * stride < n4; i += 4 * stride) {
        float4 v0 = __ldcs(src + i);
        float4 v1 = __ldcs(src + i +     stride);
        float4 v2 = __ldcs(src + i + 2 * stride);
        float4 v3 = __ldcs(src + i + 3 * stride);
        __stcs(dst + i,              v0);
        __stcs(dst + i +     stride, v1);
        __stcs(dst + i + 2 * stride, v2);
        __stcs(dst + i + 3 * stride, v3);
    }
    // Remainder
    for (; i < n4; i += stride) {
        __stcs(dst + i, __ldcs(src + i));
    }
    // Scalar tail (n_tail < 4)
    if (blockIdx.x == 0 && threadIdx.x == 0) {
        for (int t = 0; t < n_tail; t++) dst_tail[t] = src_tail[t];
    }
}

// ---------------------------------------------------------------------------
// Kernel 2: scatter-add of attention pair-products.
// One thread per (batch, pair): 8192*90 = 737,280 threads.
// ~66MB of atomic sector traffic — already near its floor (23us).
// ---------------------------------------------------------------------------
__global__ void scatter_kernel(const int*   __restrict__ obj_label,  // [BATCH, BOX]
                               const int*   __restrict__ qus_type,   // [BATCH]
                               const float* __restrict__ attention,  // [BATCH, BOX]
                               float*       __restrict__ out)        // [NUM_QT, PAIR, NUM_OT, NUM_OT]
{
    int t = blockIdx.x * blockDim.x + threadIdx.x;
    if (t >= BATCH * PAIR) return;

    int b = t / PAIR;
    int p = t - b * PAIR;

    // pair p -> (i, j): i = p/(BOX-1); j enumerates indices != i ascending.
    int i  = p / (BOX - 1);
    int jj = p - i * (BOX - 1);
    int j  = jj + (jj >= i ? 1 : 0);

    const int*   lab = obj_label + b * BOX;
    const float* att = attention + b * BOX;

    int   ol1 = lab[j];          // obj_label[b, j]
    int   ol2 = lab[i];          // obj_label[b, i]
    float val = att[j] * att[i]; // at1 * at2
    int   qt  = qus_type[b];

    size_t idx = (((size_t)qt * PAIR + p) * NUM_OT + (size_t)ol1) * NUM_OT + (size_t)ol2;
    atomicAdd(out + idx, val);
}

// ---------------------------------------------------------------------------
// Launch
// ---------------------------------------------------------------------------
extern "C" void kernel_launch(void* const* d_in, const int* in_sizes, int n_in,
                              void* d_out, int out_size)
{
    const int*   obj_label    = (const int*)  d_in[0]; // [8192,10] int32
    const int*   qus_type     = (const int*)  d_in[1]; // [8192]    int32
    const float* attention    = (const float*)d_in[2]; // [8192,10] float32
    const float* score_matrix = (const float*)d_in[3]; // [65,90,151,151] float32
    float*       out          = (float*)d_out;

    long long n  = (long long)out_size;          // 133,385,850
    long long n4 = n >> 2;                       // float4 count = 33,346,462
    int n_tail   = (int)(n - (n4 << 2));         // 2

    // Copy: saturate HBM.
    {
        int threads = 512;
        int blocks  = 148 * 8;                   // 606K threads, ~55 f4/thread
        copy_stream_kernel<<<blocks, threads>>>(
            (const float4*)score_matrix, (float4*)out, n4,
            score_matrix + (n4 << 2), out + (n4 << 2), n_tail);
    }

    // Scatter-add (same stream -> ordered after the copy).
    {
        int total   = BATCH * PAIR;              // 737,280
        int threads = 256;
        int blocks  = (total + threads - 1) / threads;
        scatter_kernel<<<blocks, threads>>>(obj_label, qus_type, attention, out);
    }
}